// round 4
// baseline (speedup 1.0000x reference)
#include <cuda_runtime.h>

// GRU_67714454389230: 2-layer GRU (H=12, IN=18) + fc(12->1), B=4096, T=512.
// Round 4: scan holds ALL recurrent weights in registers as f32x2 pairs
// (zero weight LDS per step), uses packed fma.rn.f32x2 for every dot
// (half the FMA issue), h-exchange via tiny per-warp smem, fc via shfl
// butterfly. gi0 precompute stores [b][t][u][(r,z,n,pad)] so the scan does
// one LDG.128 per lane-step.

static constexpr int IN_DIM = 18;
static constexpr int HID    = 12;
static constexpr int BATCH  = 4096;
static constexpr int SEQ    = 512;

// [b][t][u] -> float4 (gi_r, gi_z, gi_n, 0)
__device__ float4 g_gi0[(size_t)BATCH * SEQ * HID];

// ---------------- f32x2 helpers ----------------
__device__ __forceinline__ unsigned long long ffma2(unsigned long long a,
                                                    unsigned long long b,
                                                    unsigned long long c) {
    unsigned long long d;
    asm("fma.rn.f32x2 %0, %1, %2, %3;" : "=l"(d) : "l"(a), "l"(b), "l"(c));
    return d;
}
__device__ __forceinline__ float f2sum(unsigned long long v) {
    float lo, hi;
    asm("mov.b64 {%0, %1}, %2;" : "=f"(lo), "=f"(hi) : "l"(v));
    return lo + hi;
}
__device__ __forceinline__ unsigned long long fpack(float lo, float hi) {
    unsigned long long v;
    asm("mov.b64 %0, {%1, %2};" : "=l"(v) : "f"(lo), "f"(hi));
    return v;
}

__device__ __forceinline__ float fast_sig(float x) {
    return __fdividef(1.0f, 1.0f + __expf(-x));
}
__device__ __forceinline__ float fast_tanh(float x) {
    return 1.0f - __fdividef(2.0f, __expf(2.0f * x) + 1.0f);
}

// ---------------- kernel 1: gi0 = x @ W_ih0^T + b_ih0 ----------------
static constexpr int ROWS_PER_BLOCK = 64;

__global__ __launch_bounds__(128, 6)
void gi0_kernel(const float* __restrict__ x,
                const float* __restrict__ w_ih0,
                const float* __restrict__ b_ih0)
{
    __shared__ float sx[ROWS_PER_BLOCK * IN_DIM];
    __shared__ unsigned long long swp[36][9];   // weight rows as f32x2 pairs
    __shared__ float sb[36];

    const int tid = threadIdx.x;
    for (int i = tid; i < 36 * 9; i += 128) {
        const int j = i / 9, k = i % 9;
        swp[j][k] = *(const unsigned long long*)(w_ih0 + j * IN_DIM + 2 * k);
    }
    if (tid < 36) sb[tid] = b_ih0[tid];

    const size_t row0 = (size_t)blockIdx.x * ROWS_PER_BLOCK;
    const float4* xg = (const float4*)(x + row0 * IN_DIM);  // 64*18*4B: 16B-aligned blocks
    float4* sxf = (float4*)sx;
    for (int i = tid; i < (ROWS_PER_BLOCK * IN_DIM) / 4; i += 128) sxf[i] = xg[i];
    __syncthreads();

    const int row = tid >> 1;
    const int u0  = (tid & 1) * 6;     // units u0..u0+5

    unsigned long long xp[9];
    const unsigned long long* xr = (const unsigned long long*)(sx + row * IN_DIM);
#pragma unroll
    for (int i = 0; i < 9; ++i) xp[i] = xr[i];

    float4* og = g_gi0 + (row0 + row) * HID;
#pragma unroll
    for (int uu = 0; uu < 6; ++uu) {
        const int u = u0 + uu;
        float res[3];
#pragma unroll
        for (int gate = 0; gate < 3; ++gate) {
            const int j = gate * HID + u;
            unsigned long long acc = fpack(sb[j], 0.0f);
#pragma unroll
            for (int i = 0; i < 9; ++i) acc = ffma2(xp[i], swp[j][i], acc);
            res[gate] = f2sum(acc);
        }
        og[u] = make_float4(res[0], res[1], res[2], 0.0f);
    }
}

// ---------------- kernel 2: recurrent scan ----------------
// 32-thread blocks: 2 groups of 16 lanes, 1 batch per group. Lane sub<12 owns
// hidden unit `sub`; lanes 12-15 duplicate lane 11's math (discarded).
__global__ __launch_bounds__(32, 10)
void gru_scan_kernel(const float* __restrict__ w_hh0, const float* __restrict__ b_hh0,
                     const float* __restrict__ w_ih1, const float* __restrict__ w_hh1,
                     const float* __restrict__ b_ih1, const float* __restrict__ b_hh1,
                     const float* __restrict__ fc_w, const float* __restrict__ fc_b,
                     float* __restrict__ out)
{
    __shared__ __align__(16) float s_h1[2][HID];
    __shared__ __align__(16) float s_h2[2][HID];

    const int tid = threadIdx.x;
    const int grp = tid >> 4;
    const int sub = tid & 15;
    const int u   = (sub < HID) ? sub : HID - 1;
    const int batch = blockIdx.x * 2 + grp;

    // Per-lane weight rows, packed as f32x2 pairs (loaded once; stays in regs).
    unsigned long long whh0[3][6], whh1[3][6], wih1[3][6];
#pragma unroll
    for (int g = 0; g < 3; ++g) {
        const unsigned long long* p0 = (const unsigned long long*)(w_hh0 + (g * HID + u) * HID);
        const unsigned long long* p1 = (const unsigned long long*)(w_hh1 + (g * HID + u) * HID);
        const unsigned long long* p2 = (const unsigned long long*)(w_ih1 + (g * HID + u) * HID);
#pragma unroll
        for (int i = 0; i < 6; ++i) {
            whh0[g][i] = p0[i]; whh1[g][i] = p1[i]; wih1[g][i] = p2[i];
        }
    }

    const float bh0r = b_hh0[u];
    const float bh0z = b_hh0[HID + u];
    const unsigned long long pbh0n = fpack(b_hh0[2 * HID + u], 0.0f);
    const unsigned long long pb2r  = fpack(b_ih1[u]           + b_hh1[u],          0.0f);
    const unsigned long long pb2z  = fpack(b_ih1[HID + u]     + b_hh1[HID + u],    0.0f);
    const unsigned long long pb2in = fpack(b_ih1[2 * HID + u], 0.0f);
    const unsigned long long pb2hn = fpack(b_hh1[2 * HID + u], 0.0f);
    const float fcw_u = (sub < HID) ? fc_w[u] : 0.0f;
    const float fcb = fc_b[0];

    unsigned long long h1p[6], h2p[6];
#pragma unroll
    for (int i = 0; i < 6; ++i) { h1p[i] = 0ull; h2p[i] = 0ull; }
    float hprev1 = 0.0f, hprev2 = 0.0f;

    const float4* gp = g_gi0 + (size_t)batch * SEQ * HID + u;
    float* op = out + (size_t)batch * SEQ;

    float4 gc = gp[0];

    for (int t = 0; t < SEQ; ++t) {
        const int tn = (t + 1 < SEQ) ? (t + 1) : t;
        const float4 gn = gp[(size_t)tn * HID];     // prefetch next step's gi

        // ---- layer-2 hh1 dots from PREVIOUS h2 (packed) ----
        unsigned long long pr = pb2r, pz = pb2z, pnh = pb2hn;
#pragma unroll
        for (int i = 0; i < 6; ++i) {
            pr  = ffma2(h2p[i], whh1[0][i], pr);
            pz  = ffma2(h2p[i], whh1[1][i], pz);
            pnh = ffma2(h2p[i], whh1[2][i], pnh);
        }
        const float a2hn = f2sum(pnh);

        // ---- layer 1 ----
        unsigned long long qr = fpack(gc.x, bh0r);
        unsigned long long qz = fpack(gc.y, bh0z);
        unsigned long long qn = pbh0n;
#pragma unroll
        for (int i = 0; i < 6; ++i) {
            qr = ffma2(h1p[i], whh0[0][i], qr);
            qz = ffma2(h1p[i], whh0[1][i], qz);
            qn = ffma2(h1p[i], whh0[2][i], qn);
        }
        const float r1 = fast_sig(f2sum(qr));
        const float z1 = fast_sig(f2sum(qz));
        const float n1 = fast_tanh(fmaf(r1, f2sum(qn), gc.z));
        const float hn1 = fmaf(z1, hprev1 - n1, n1);
        hprev1 = hn1;

        if (sub < HID) s_h1[grp][u] = hn1;
        __syncwarp();
        {
            const ulonglong2* hp = (const ulonglong2*)s_h1[grp];
            const ulonglong2 a = hp[0], b = hp[1], c = hp[2];
            h1p[0] = a.x; h1p[1] = a.y; h1p[2] = b.x;
            h1p[3] = b.y; h1p[4] = c.x; h1p[5] = c.y;
        }

        // ---- layer-2 ih1 dots on fresh h1 ----
        unsigned long long pin = pb2in;
#pragma unroll
        for (int i = 0; i < 6; ++i) {
            pr  = ffma2(h1p[i], wih1[0][i], pr);
            pz  = ffma2(h1p[i], wih1[1][i], pz);
            pin = ffma2(h1p[i], wih1[2][i], pin);
        }
        const float r2 = fast_sig(f2sum(pr));
        const float z2 = fast_sig(f2sum(pz));
        const float n2 = fast_tanh(fmaf(r2, a2hn, f2sum(pin)));
        const float hn2 = fmaf(z2, hprev2 - n2, n2);
        hprev2 = hn2;

        if (sub < HID) s_h2[grp][u] = hn2;
        __syncwarp();
        {
            const ulonglong2* hp = (const ulonglong2*)s_h2[grp];
            const ulonglong2 a = hp[0], b = hp[1], c = hp[2];
            h2p[0] = a.x; h2p[1] = a.y; h2p[2] = b.x;
            h2p[3] = b.y; h2p[4] = c.x; h2p[5] = c.y;
        }

        // ---- fc: butterfly reduce fcw_u * hn2 over the 16-lane group ----
        float v = fcw_u * hn2;      // lanes 12-15 contribute 0
        v += __shfl_xor_sync(0xffffffffu, v, 8, 16);
        v += __shfl_xor_sync(0xffffffffu, v, 4, 16);
        v += __shfl_xor_sync(0xffffffffu, v, 2, 16);
        v += __shfl_xor_sync(0xffffffffu, v, 1, 16);
        if (sub == 0) op[t] = v + fcb;

        gc = gn;
    }
}

extern "C" void kernel_launch(void* const* d_in, const int* in_sizes, int n_in,
                              void* d_out, int out_size) {
    const float* x     = (const float*)d_in[0];
    const float* w_ih0 = (const float*)d_in[1];
    const float* w_hh0 = (const float*)d_in[2];
    const float* b_ih0 = (const float*)d_in[3];
    const float* b_hh0 = (const float*)d_in[4];
    const float* w_ih1 = (const float*)d_in[5];
    const float* w_hh1 = (const float*)d_in[6];
    const float* b_ih1 = (const float*)d_in[7];
    const float* b_hh1 = (const float*)d_in[8];
    const float* fc_w  = (const float*)d_in[9];
    const float* fc_b  = (const float*)d_in[10];
    float* out = (float*)d_out;

    gi0_kernel<<<(BATCH * SEQ) / ROWS_PER_BLOCK, 128>>>(x, w_ih0, b_ih0);
    gru_scan_kernel<<<BATCH / 2, 32>>>(w_hh0, b_hh0, w_ih1, w_hh1,
                                       b_ih1, b_hh1, fc_w, fc_b, out);
}

// round 5
// speedup vs baseline: 1.3785x; 1.3785x over previous
#include <cuda_runtime.h>

// GRU_67714454389230: 2-layer GRU (H=12, IN=18) + fc(12->1), B=4096, T=512.
// Round 5: merge R3 (2 batches/group ILP) with R4 (f32x2 register weights).
//  - scan: 16-lane groups, 2 batches each; w_hh0 & w_ih1 in registers (f32x2),
//    w_hh1 in smem (fed to the early, latency-tolerant hh2 dots);
//    h-exchange via per-group smem; fc via width-16 shfl butterfly.
//  - gi0: smem-staged, fully coalesced output writes.

static constexpr int IN_DIM = 18;
static constexpr int HID    = 12;
static constexpr int BATCH  = 4096;
static constexpr int SEQ    = 512;

typedef unsigned long long ull;

// [row = b*SEQ+t][u] -> float4 (gi_r, gi_z, gi_n, 0)
__device__ float4 g_gi0[(size_t)BATCH * SEQ * HID];

// ---------------- f32x2 helpers ----------------
__device__ __forceinline__ ull ffma2(ull a, ull b, ull c) {
    ull d;
    asm("fma.rn.f32x2 %0, %1, %2, %3;" : "=l"(d) : "l"(a), "l"(b), "l"(c));
    return d;
}
__device__ __forceinline__ float f2sum(ull v) {
    float lo, hi;
    asm("mov.b64 {%0, %1}, %2;" : "=f"(lo), "=f"(hi) : "l"(v));
    return lo + hi;
}
__device__ __forceinline__ ull fpack(float lo, float hi) {
    ull v;
    asm("mov.b64 %0, {%1, %2};" : "=l"(v) : "f"(lo), "f"(hi));
    return v;
}
__device__ __forceinline__ float fast_sig(float x) {
    return __fdividef(1.0f, 1.0f + __expf(-x));
}
__device__ __forceinline__ float fast_tanh(float x) {
    return 1.0f - __fdividef(2.0f, __expf(2.0f * x) + 1.0f);
}

// ---------------- kernel 1: gi0 = x @ W_ih0^T + b_ih0 ----------------
// 128 threads, 128 rows per block, 1 row per thread. Outputs staged in smem
// and flushed with coalesced STG.128.
static constexpr int GI_ROWS = 128;

__global__ __launch_bounds__(128, 4)
void gi0_kernel(const float* __restrict__ x,
                const float* __restrict__ w_ih0,
                const float* __restrict__ b_ih0)
{
    __shared__ float  s_x[GI_ROWS * IN_DIM];     // 9 KB
    __shared__ ull    s_w[36][9];                // 2.5 KB, f32x2 weight pairs
    __shared__ float  s_b[36];
    __shared__ float4 s_out[GI_ROWS][HID];       // 24 KB

    const int tid = threadIdx.x;
    for (int i = tid; i < 36 * 9; i += 128) {
        const int j = i / 9, k = i % 9;
        s_w[j][k] = *(const ull*)(w_ih0 + j * IN_DIM + 2 * k);
    }
    if (tid < 36) s_b[tid] = b_ih0[tid];

    const size_t row0 = (size_t)blockIdx.x * GI_ROWS;
    {   // coalesced x stage: 128*18 floats = 576 float4 (16B-aligned block base)
        const float4* xg = (const float4*)(x + row0 * IN_DIM);
        float4* sx4 = (float4*)s_x;
        for (int i = tid; i < (GI_ROWS * IN_DIM) / 4; i += 128) sx4[i] = xg[i];
    }
    __syncthreads();

    // each thread: one row
    ull xp[9];
    {
        const ull* xr = (const ull*)(s_x + tid * IN_DIM);   // 72B stride, 8B aligned
#pragma unroll
        for (int i = 0; i < 9; ++i) xp[i] = xr[i];
    }
#pragma unroll
    for (int u = 0; u < HID; ++u) {
        float res[3];
#pragma unroll
        for (int g = 0; g < 3; ++g) {
            const int j = g * HID + u;
            ull acc = fpack(s_b[j], 0.0f);
#pragma unroll
            for (int k = 0; k < 9; ++k) acc = ffma2(xp[k], s_w[j][k], acc);
            res[g] = f2sum(acc);
        }
        s_out[tid][u] = make_float4(res[0], res[1], res[2], 0.0f);
    }
    __syncthreads();

    {   // coalesced flush: 128*12 float4 = 1536 float4
        float4* og = (float4*)(g_gi0 + row0 * HID);
        const float4* so = (const float4*)s_out;
        for (int i = tid; i < GI_ROWS * HID; i += 128) og[i] = so[i];
    }
}

// ---------------- kernel 2: recurrent scan ----------------
// 128-thread blocks = 8 groups of 16 lanes; each group handles 2 batches.
// Lane sub<12 owns hidden unit `sub`; lanes 12-15 duplicate lane 11 (discarded).
static constexpr int S_THREADS = 128;
static constexpr int S_GRID    = BATCH / (8 * 2);   // 256 blocks

__global__ __launch_bounds__(S_THREADS)
void gru_scan_kernel(const float* __restrict__ w_hh0, const float* __restrict__ b_hh0,
                     const float* __restrict__ w_ih1, const float* __restrict__ w_hh1,
                     const float* __restrict__ b_ih1, const float* __restrict__ b_hh1,
                     const float* __restrict__ fc_w, const float* __restrict__ fc_b,
                     float* __restrict__ out)
{
    __shared__ ull s_whh1[3][6][HID];                  // [gate][pair][unit], 1.7 KB
    __shared__ __align__(16) float s_h1[8][2][HID];    // [group][batch][unit]
    __shared__ __align__(16) float s_h2[8][2][HID];

    const int tid   = threadIdx.x;
    const int grp_l = tid >> 4;
    const int sub   = tid & 15;
    const int u     = (sub < HID) ? sub : HID - 1;
    const int G     = blockIdx.x * 8 + grp_l;
    const int bA    = G * 2;
    const int bB    = bA + 1;

    if (tid < 36) {
        const int g = tid / HID, uu = tid % HID;
        const ull* wr = (const ull*)(w_hh1 + (g * HID + uu) * HID);
#pragma unroll
        for (int i = 0; i < 6; ++i) s_whh1[g][i][uu] = wr[i];
    }
    __syncthreads();

    // Critical-path weights in registers (f32x2 pairs).
    ull whh0[3][6], wih1[3][6];
#pragma unroll
    for (int g = 0; g < 3; ++g) {
        const ull* p0 = (const ull*)(w_hh0 + (g * HID + u) * HID);
        const ull* p1 = (const ull*)(w_ih1 + (g * HID + u) * HID);
#pragma unroll
        for (int i = 0; i < 6; ++i) { whh0[g][i] = p0[i]; wih1[g][i] = p1[i]; }
    }

    const float bh0r = b_hh0[u];
    const float bh0z = b_hh0[HID + u];
    const ull pbh0n = fpack(b_hh0[2 * HID + u], 0.0f);
    const ull pb2r  = fpack(b_ih1[u]           + b_hh1[u],          0.0f);
    const ull pb2z  = fpack(b_ih1[HID + u]     + b_hh1[HID + u],    0.0f);
    const ull pb2in = fpack(b_ih1[2 * HID + u], 0.0f);
    const ull pb2hn = fpack(b_hh1[2 * HID + u], 0.0f);
    const float fcw_u = (sub < HID) ? fc_w[u] : 0.0f;
    const float fcb = fc_b[0];

    ull h1A[6], h1B[6], h2A[6], h2B[6];
#pragma unroll
    for (int i = 0; i < 6; ++i) { h1A[i] = h1B[i] = h2A[i] = h2B[i] = 0ull; }
    float hp1A = 0.0f, hp1B = 0.0f, hp2A = 0.0f, hp2B = 0.0f;

    const float4* gpA = g_gi0 + (size_t)bA * SEQ * HID + u;
    const float4* gpB = g_gi0 + (size_t)bB * SEQ * HID + u;

    float4 gcA = gpA[0];
    float4 gcB = gpB[0];

#pragma unroll 1
    for (int t = 0; t < SEQ; ++t) {
        const int tn = (t + 1 < SEQ) ? (t + 1) : t;
        const float4 gnA = gpA[(size_t)tn * HID];
        const float4 gnB = gpB[(size_t)tn * HID];

        // ---- layer-2 hh dots from PREVIOUS h2 (weights from smem; latency-tolerant) ----
        ull prA = pb2r, pzA = pb2z, pnA = pb2hn;
        ull prB = pb2r, pzB = pb2z, pnB = pb2hn;
#pragma unroll
        for (int i = 0; i < 6; ++i) {
            const ull wr = s_whh1[0][i][u];
            const ull wz = s_whh1[1][i][u];
            const ull wn = s_whh1[2][i][u];
            prA = ffma2(h2A[i], wr, prA); prB = ffma2(h2B[i], wr, prB);
            pzA = ffma2(h2A[i], wz, pzA); pzB = ffma2(h2B[i], wz, pzB);
            pnA = ffma2(h2A[i], wn, pnA); pnB = ffma2(h2B[i], wn, pnB);
        }
        const float a2hnA = f2sum(pnA);
        const float a2hnB = f2sum(pnB);

        // ---- layer 1 (register weights) ----
        ull qrA = fpack(gcA.x, bh0r), qzA = fpack(gcA.y, bh0z), qnA = pbh0n;
        ull qrB = fpack(gcB.x, bh0r), qzB = fpack(gcB.y, bh0z), qnB = pbh0n;
#pragma unroll
        for (int i = 0; i < 6; ++i) {
            qrA = ffma2(h1A[i], whh0[0][i], qrA); qrB = ffma2(h1B[i], whh0[0][i], qrB);
            qzA = ffma2(h1A[i], whh0[1][i], qzA); qzB = ffma2(h1B[i], whh0[1][i], qzB);
            qnA = ffma2(h1A[i], whh0[2][i], qnA); qnB = ffma2(h1B[i], whh0[2][i], qnB);
        }
        const float r1A = fast_sig(f2sum(qrA));
        const float r1B = fast_sig(f2sum(qrB));
        const float z1A = fast_sig(f2sum(qzA));
        const float z1B = fast_sig(f2sum(qzB));
        const float n1A = fast_tanh(fmaf(r1A, f2sum(qnA), gcA.z));
        const float n1B = fast_tanh(fmaf(r1B, f2sum(qnB), gcB.z));
        const float hn1A = fmaf(z1A, hp1A - n1A, n1A);
        const float hn1B = fmaf(z1B, hp1B - n1B, n1B);
        hp1A = hn1A; hp1B = hn1B;

        if (sub < HID) { s_h1[grp_l][0][u] = hn1A; s_h1[grp_l][1][u] = hn1B; }
        __syncwarp();
        {
            const ulonglong2* pa = (const ulonglong2*)s_h1[grp_l][0];
            const ulonglong2* pb = (const ulonglong2*)s_h1[grp_l][1];
            const ulonglong2 a0 = pa[0], a1 = pa[1], a2 = pa[2];
            const ulonglong2 b0 = pb[0], b1 = pb[1], b2 = pb[2];
            h1A[0] = a0.x; h1A[1] = a0.y; h1A[2] = a1.x;
            h1A[3] = a1.y; h1A[4] = a2.x; h1A[5] = a2.y;
            h1B[0] = b0.x; h1B[1] = b0.y; h1B[2] = b1.x;
            h1B[3] = b1.y; h1B[4] = b2.x; h1B[5] = b2.y;
        }

        // ---- layer-2 ih dots on fresh h1 (register weights) ----
        ull piA = pb2in, piB = pb2in;
#pragma unroll
        for (int i = 0; i < 6; ++i) {
            prA = ffma2(h1A[i], wih1[0][i], prA); prB = ffma2(h1B[i], wih1[0][i], prB);
            pzA = ffma2(h1A[i], wih1[1][i], pzA); pzB = ffma2(h1B[i], wih1[1][i], pzB);
            piA = ffma2(h1A[i], wih1[2][i], piA); piB = ffma2(h1B[i], wih1[2][i], piB);
        }
        const float r2A = fast_sig(f2sum(prA));
        const float r2B = fast_sig(f2sum(prB));
        const float z2A = fast_sig(f2sum(pzA));
        const float z2B = fast_sig(f2sum(pzB));
        const float n2A = fast_tanh(fmaf(r2A, a2hnA, f2sum(piA)));
        const float n2B = fast_tanh(fmaf(r2B, a2hnB, f2sum(piB)));
        const float hn2A = fmaf(z2A, hp2A - n2A, n2A);
        const float hn2B = fmaf(z2B, hp2B - n2B, n2B);
        hp2A = hn2A; hp2B = hn2B;

        if (sub < HID) { s_h2[grp_l][0][u] = hn2A; s_h2[grp_l][1][u] = hn2B; }
        __syncwarp();
        {
            const ulonglong2* pa = (const ulonglong2*)s_h2[grp_l][0];
            const ulonglong2* pb = (const ulonglong2*)s_h2[grp_l][1];
            const ulonglong2 a0 = pa[0], a1 = pa[1], a2 = pa[2];
            const ulonglong2 b0 = pb[0], b1 = pb[1], b2 = pb[2];
            h2A[0] = a0.x; h2A[1] = a0.y; h2A[2] = a1.x;
            h2A[3] = a1.y; h2A[4] = a2.x; h2A[5] = a2.y;
            h2B[0] = b0.x; h2B[1] = b0.y; h2B[2] = b1.x;
            h2B[3] = b1.y; h2B[4] = b2.x; h2B[5] = b2.y;
        }

        // ---- fc: two width-16 butterfly reductions (lanes 12-15 contribute 0) ----
        float vA = fcw_u * hn2A;
        float vB = fcw_u * hn2B;
        vA += __shfl_xor_sync(0xffffffffu, vA, 8, 16);
        vB += __shfl_xor_sync(0xffffffffu, vB, 8, 16);
        vA += __shfl_xor_sync(0xffffffffu, vA, 4, 16);
        vB += __shfl_xor_sync(0xffffffffu, vB, 4, 16);
        vA += __shfl_xor_sync(0xffffffffu, vA, 2, 16);
        vB += __shfl_xor_sync(0xffffffffu, vB, 2, 16);
        vA += __shfl_xor_sync(0xffffffffu, vA, 1, 16);
        vB += __shfl_xor_sync(0xffffffffu, vB, 1, 16);
        if (sub == 0) {
            out[(size_t)bA * SEQ + t] = vA + fcb;
            out[(size_t)bB * SEQ + t] = vB + fcb;
        }

        gcA = gnA; gcB = gnB;
    }
}

extern "C" void kernel_launch(void* const* d_in, const int* in_sizes, int n_in,
                              void* d_out, int out_size) {
    const float* x     = (const float*)d_in[0];
    const float* w_ih0 = (const float*)d_in[1];
    const float* w_hh0 = (const float*)d_in[2];
    const float* b_ih0 = (const float*)d_in[3];
    const float* b_hh0 = (const float*)d_in[4];
    const float* w_ih1 = (const float*)d_in[5];
    const float* w_hh1 = (const float*)d_in[6];
    const float* b_ih1 = (const float*)d_in[7];
    const float* b_hh1 = (const float*)d_in[8];
    const float* fc_w  = (const float*)d_in[9];
    const float* fc_b  = (const float*)d_in[10];
    float* out = (float*)d_out;

    gi0_kernel<<<(BATCH * SEQ) / GI_ROWS, 128>>>(x, w_ih0, b_ih0);
    gru_scan_kernel<<<S_GRID, S_THREADS>>>(w_hh0, b_hh0, w_ih1, w_hh1,
                                           b_ih1, b_hh1, fc_w, fc_b, out);
}

// round 6
// speedup vs baseline: 2.0427x; 1.4818x over previous
#include <cuda_runtime.h>

// GRU_67714454389230: 2-layer GRU (H=12, IN=18) + fc(12->1), B=4096, T=512.
// Round 6:
//  - gi0: 4 rows/thread (4x weight-LDS reuse), conflict-free padded smem x,
//    PLANE output layout [u][B*T] with coalesced writes.
//  - scan: all recurrent weights in registers (f32x2); sigmoids via
//    tanh.approx.f32 (n-gate tanh stays exact-exp); fc on idle lanes 12/13.

static constexpr int IN_DIM = 18;
static constexpr int HID    = 12;
static constexpr int BATCH  = 4096;
static constexpr int SEQ    = 512;
static constexpr size_t NROWS = (size_t)BATCH * SEQ;   // 2,097,152

typedef unsigned long long ull;

// plane layout: g_gi0[u * NROWS + row] = float4(gi_r, gi_z, gi_n, 0), row = b*SEQ+t
__device__ float4 g_gi0[HID * NROWS];

// ---------------- helpers ----------------
__device__ __forceinline__ ull ffma2(ull a, ull b, ull c) {
    ull d;
    asm("fma.rn.f32x2 %0, %1, %2, %3;" : "=l"(d) : "l"(a), "l"(b), "l"(c));
    return d;
}
__device__ __forceinline__ float f2sum(ull v) {
    float lo, hi;
    asm("mov.b64 {%0, %1}, %2;" : "=f"(lo), "=f"(hi) : "l"(v));
    return lo + hi;
}
__device__ __forceinline__ ull fpack(float lo, float hi) {
    ull v;
    asm("mov.b64 %0, {%1, %2};" : "=l"(v) : "f"(lo), "f"(hi));
    return v;
}
__device__ __forceinline__ float tanhapx(float x) {
    float y;
    asm("tanh.approx.f32 %0, %1;" : "=f"(y) : "f"(x));
    return y;
}
__device__ __forceinline__ float fast_sig(float x) {        // via HW tanh
    return fmaf(tanhapx(0.5f * x), 0.5f, 0.5f);
}
__device__ __forceinline__ float exact_tanh(float x) {      // exact-ish for n gate
    return 1.0f - __fdividef(2.0f, __expf(2.0f * x) + 1.0f);
}

// ---------------- kernel 1: gi0 = x @ W_ih0^T + b_ih0 ----------------
// 128 threads x 4 rows = 512 rows/block; thread j-th row = tid + j*128.
static constexpr int GI_ROWS = 512;

__global__ __launch_bounds__(128, 4)
void gi0_kernel(const float* __restrict__ x,
                const float* __restrict__ w_ih0,
                const float* __restrict__ b_ih0)
{
    __shared__ ull   s_xu[GI_ROWS * 11];   // 9 pairs + pad to 11 -> conflict-free
    __shared__ ull   s_w[36][9];
    __shared__ float s_b[36];

    const int tid = threadIdx.x;
    for (int i = tid; i < 36 * 9; i += 128) {
        const int j = i / 9, k = i % 9;
        s_w[j][k] = *(const ull*)(w_ih0 + j * IN_DIM + 2 * k);
    }
    if (tid < 36) s_b[tid] = b_ih0[tid];

    const size_t row0 = (size_t)blockIdx.x * GI_ROWS;
    const float* xg = x + row0 * IN_DIM;
    for (int i = tid; i < GI_ROWS * 9; i += 128) {
        const int r = i / 9, p = i % 9;
        s_xu[r * 11 + p] = *(const ull*)(xg + r * IN_DIM + 2 * p);
    }
    __syncthreads();

    ull xp[4][9];
#pragma unroll
    for (int j = 0; j < 4; ++j) {
        const ull* row = s_xu + (tid + j * 128) * 11;
#pragma unroll
        for (int k = 0; k < 9; ++k) xp[j][k] = row[k];
    }

#pragma unroll
    for (int u = 0; u < HID; ++u) {
        float res[4][3];
#pragma unroll
        for (int g = 0; g < 3; ++g) {
            const int jrow = g * HID + u;
            ull w[9];
#pragma unroll
            for (int k = 0; k < 9; ++k) w[k] = s_w[jrow][k];
            const float b = s_b[jrow];
#pragma unroll
            for (int j = 0; j < 4; ++j) {
                ull acc = fpack(b, 0.0f);
#pragma unroll
                for (int k = 0; k < 9; ++k) acc = ffma2(xp[j][k], w[k], acc);
                res[j][g] = f2sum(acc);
            }
        }
        float4* plane = g_gi0 + (size_t)u * NROWS + row0;
#pragma unroll
        for (int j = 0; j < 4; ++j)
            plane[tid + j * 128] = make_float4(res[j][0], res[j][1], res[j][2], 0.0f);
    }
}

// ---------------- kernel 2: recurrent scan ----------------
// 128-thread blocks = 8 groups of 16 lanes; 2 batches per group.
static constexpr int S_THREADS = 128;
static constexpr int S_GRID    = BATCH / (8 * 2);   // 256 blocks

__global__ __launch_bounds__(S_THREADS)
void gru_scan_kernel(const float* __restrict__ w_hh0, const float* __restrict__ b_hh0,
                     const float* __restrict__ w_ih1, const float* __restrict__ w_hh1,
                     const float* __restrict__ b_ih1, const float* __restrict__ b_hh1,
                     const float* __restrict__ fc_w, const float* __restrict__ fc_b,
                     float* __restrict__ out)
{
    __shared__ __align__(16) float s_h1[8][2][HID];
    __shared__ __align__(16) float s_h2[8][2][HID];

    const int tid   = threadIdx.x;
    const int grp_l = tid >> 4;
    const int sub   = tid & 15;
    const int u     = (sub < HID) ? sub : HID - 1;
    const int G     = blockIdx.x * 8 + grp_l;
    const int bA    = G * 2;
    const int bB    = bA + 1;

    // All recurrent weights in registers (f32x2 pairs).
    ull whh0[3][6], wih1[3][6], whh1[3][6];
#pragma unroll
    for (int g = 0; g < 3; ++g) {
        const ull* p0 = (const ull*)(w_hh0 + (g * HID + u) * HID);
        const ull* p1 = (const ull*)(w_ih1 + (g * HID + u) * HID);
        const ull* p2 = (const ull*)(w_hh1 + (g * HID + u) * HID);
#pragma unroll
        for (int i = 0; i < 6; ++i) {
            whh0[g][i] = p0[i]; wih1[g][i] = p1[i]; whh1[g][i] = p2[i];
        }
    }

    const float bh0r = b_hh0[u];
    const float bh0z = b_hh0[HID + u];
    const ull pbh0n = fpack(b_hh0[2 * HID + u], 0.0f);
    const ull pb2r  = fpack(b_ih1[u]           + b_hh1[u],          0.0f);
    const ull pb2z  = fpack(b_ih1[HID + u]     + b_hh1[HID + u],    0.0f);
    const ull pb2in = fpack(b_ih1[2 * HID + u], 0.0f);
    const ull pb2hn = fpack(b_hh1[2 * HID + u], 0.0f);
    const float fcb = fc_b[0];
    ull fcwp[6];
#pragma unroll
    for (int i = 0; i < 6; ++i) fcwp[i] = *(const ull*)(fc_w + 2 * i);

    ull h1A[6], h1B[6], h2A[6], h2B[6];
#pragma unroll
    for (int i = 0; i < 6; ++i) { h1A[i] = h1B[i] = h2A[i] = h2B[i] = 0ull; }
    float hp1A = 0.0f, hp1B = 0.0f, hp2A = 0.0f, hp2B = 0.0f;

    // plane pointers: consecutive t -> consecutive float4
    const float4* gpA = g_gi0 + (size_t)u * NROWS + (size_t)bA * SEQ;
    const float4* gpB = g_gi0 + (size_t)u * NROWS + (size_t)bB * SEQ;

    float4 gcA = gpA[0];
    float4 gcB = gpB[0];

#pragma unroll 1
    for (int t = 0; t < SEQ; ++t) {
        const int tn = (t + 1 < SEQ) ? (t + 1) : t;
        const float4 gnA = gpA[tn];
        const float4 gnB = gpB[tn];

        // ---- layer-2 hh dots from PREVIOUS h2 ----
        ull prA = pb2r, pzA = pb2z, pnA = pb2hn;
        ull prB = pb2r, pzB = pb2z, pnB = pb2hn;
#pragma unroll
        for (int i = 0; i < 6; ++i) {
            prA = ffma2(h2A[i], whh1[0][i], prA); prB = ffma2(h2B[i], whh1[0][i], prB);
            pzA = ffma2(h2A[i], whh1[1][i], pzA); pzB = ffma2(h2B[i], whh1[1][i], pzB);
            pnA = ffma2(h2A[i], whh1[2][i], pnA); pnB = ffma2(h2B[i], whh1[2][i], pnB);
        }
        const float a2hnA = f2sum(pnA);
        const float a2hnB = f2sum(pnB);

        // ---- layer 1 ----
        ull qrA = fpack(gcA.x, bh0r), qzA = fpack(gcA.y, bh0z), qnA = pbh0n;
        ull qrB = fpack(gcB.x, bh0r), qzB = fpack(gcB.y, bh0z), qnB = pbh0n;
#pragma unroll
        for (int i = 0; i < 6; ++i) {
            qrA = ffma2(h1A[i], whh0[0][i], qrA); qrB = ffma2(h1B[i], whh0[0][i], qrB);
            qzA = ffma2(h1A[i], whh0[1][i], qzA); qzB = ffma2(h1B[i], whh0[1][i], qzB);
            qnA = ffma2(h1A[i], whh0[2][i], qnA); qnB = ffma2(h1B[i], whh0[2][i], qnB);
        }
        const float r1A = fast_sig(f2sum(qrA));
        const float r1B = fast_sig(f2sum(qrB));
        const float z1A = fast_sig(f2sum(qzA));
        const float z1B = fast_sig(f2sum(qzB));
        const float n1A = exact_tanh(fmaf(r1A, f2sum(qnA), gcA.z));
        const float n1B = exact_tanh(fmaf(r1B, f2sum(qnB), gcB.z));
        const float hn1A = fmaf(z1A, hp1A - n1A, n1A);
        const float hn1B = fmaf(z1B, hp1B - n1B, n1B);
        hp1A = hn1A; hp1B = hn1B;

        if (sub < HID) { s_h1[grp_l][0][u] = hn1A; s_h1[grp_l][1][u] = hn1B; }
        __syncwarp();
        {
            const ulonglong2* pa = (const ulonglong2*)s_h1[grp_l][0];
            const ulonglong2* pb = (const ulonglong2*)s_h1[grp_l][1];
            const ulonglong2 a0 = pa[0], a1 = pa[1], a2 = pa[2];
            const ulonglong2 b0 = pb[0], b1 = pb[1], b2 = pb[2];
            h1A[0] = a0.x; h1A[1] = a0.y; h1A[2] = a1.x;
            h1A[3] = a1.y; h1A[4] = a2.x; h1A[5] = a2.y;
            h1B[0] = b0.x; h1B[1] = b0.y; h1B[2] = b1.x;
            h1B[3] = b1.y; h1B[4] = b2.x; h1B[5] = b2.y;
        }

        // ---- layer-2 ih dots on fresh h1 ----
        ull piA = pb2in, piB = pb2in;
#pragma unroll
        for (int i = 0; i < 6; ++i) {
            prA = ffma2(h1A[i], wih1[0][i], prA); prB = ffma2(h1B[i], wih1[0][i], prB);
            pzA = ffma2(h1A[i], wih1[1][i], pzA); pzB = ffma2(h1B[i], wih1[1][i], pzB);
            piA = ffma2(h1A[i], wih1[2][i], piA); piB = ffma2(h1B[i], wih1[2][i], piB);
        }
        const float r2A = fast_sig(f2sum(prA));
        const float r2B = fast_sig(f2sum(prB));
        const float z2A = fast_sig(f2sum(pzA));
        const float z2B = fast_sig(f2sum(pzB));
        const float n2A = exact_tanh(fmaf(r2A, a2hnA, f2sum(piA)));
        const float n2B = exact_tanh(fmaf(r2B, a2hnB, f2sum(piB)));
        const float hn2A = fmaf(z2A, hp2A - n2A, n2A);
        const float hn2B = fmaf(z2B, hp2B - n2B, n2B);
        hp2A = hn2A; hp2B = hn2B;

        if (sub < HID) { s_h2[grp_l][0][u] = hn2A; s_h2[grp_l][1][u] = hn2B; }
        __syncwarp();
        {
            const ulonglong2* pa = (const ulonglong2*)s_h2[grp_l][0];
            const ulonglong2* pb = (const ulonglong2*)s_h2[grp_l][1];
            const ulonglong2 a0 = pa[0], a1 = pa[1], a2 = pa[2];
            const ulonglong2 b0 = pb[0], b1 = pb[1], b2 = pb[2];
            h2A[0] = a0.x; h2A[1] = a0.y; h2A[2] = a1.x;
            h2A[3] = a1.y; h2A[4] = a2.x; h2A[5] = a2.y;
            h2B[0] = b0.x; h2B[1] = b0.y; h2B[2] = b1.x;
            h2B[3] = b1.y; h2B[4] = b2.x; h2B[5] = b2.y;
        }

        // ---- fc on idle lanes 12 (batch A) / 13 (batch B) ----
        if (sub == 12 || sub == 13) {
            const ull* hh = (sub == 12) ? h2A : h2B;
            ull acc = fpack(fcb, 0.0f);
#pragma unroll
            for (int i = 0; i < 6; ++i) acc = ffma2(hh[i], fcwp[i], acc);
            out[(size_t)((sub == 12) ? bA : bB) * SEQ + t] = f2sum(acc);
        }

        gcA = gnA; gcB = gnB;
    }
}

extern "C" void kernel_launch(void* const* d_in, const int* in_sizes, int n_in,
                              void* d_out, int out_size) {
    const float* x     = (const float*)d_in[0];
    const float* w_ih0 = (const float*)d_in[1];
    const float* w_hh0 = (const float*)d_in[2];
    const float* b_ih0 = (const float*)d_in[3];
    const float* b_hh0 = (const float*)d_in[4];
    const float* w_ih1 = (const float*)d_in[5];
    const float* w_hh1 = (const float*)d_in[6];
    const float* b_ih1 = (const float*)d_in[7];
    const float* b_hh1 = (const float*)d_in[8];
    const float* fc_w  = (const float*)d_in[9];
    const float* fc_b  = (const float*)d_in[10];
    float* out = (float*)d_out;

    gi0_kernel<<<(int)(NROWS / GI_ROWS), 128>>>(x, w_ih0, b_ih0);
    gru_scan_kernel<<<S_GRID, S_THREADS>>>(w_hh0, b_hh0, w_ih1, w_hh1,
                                           b_ih1, b_hh1, fc_w, fc_b, out);
}

// round 7
// speedup vs baseline: 2.1874x; 1.0708x over previous
#include <cuda_runtime.h>

// GRU_67714454389230: 2-layer GRU (H=12, IN=18) + fc(12->1), B=4096, T=512.
// Round 7 (from R6):
//  - scan blocks shrunk 128 -> 32 threads (grid 256 -> 1024) to kill wave
//    quantization (108 SMs had 2x the load of the other 40).
//  - ALL activations via HW tanh.approx.f32 (n-gate too): MUFU count halved,
//    ~60 cyc of serial EX2->RCP removed from the per-step critical path.
//  - gi0 unchanged (near DRAM floor).

static constexpr int IN_DIM = 18;
static constexpr int HID    = 12;
static constexpr int BATCH  = 4096;
static constexpr int SEQ    = 512;
static constexpr size_t NROWS = (size_t)BATCH * SEQ;   // 2,097,152

typedef unsigned long long ull;

// plane layout: g_gi0[u * NROWS + row] = float4(gi_r, gi_z, gi_n, 0), row = b*SEQ+t
__device__ float4 g_gi0[HID * NROWS];

// ---------------- helpers ----------------
__device__ __forceinline__ ull ffma2(ull a, ull b, ull c) {
    ull d;
    asm("fma.rn.f32x2 %0, %1, %2, %3;" : "=l"(d) : "l"(a), "l"(b), "l"(c));
    return d;
}
__device__ __forceinline__ float f2sum(ull v) {
    float lo, hi;
    asm("mov.b64 {%0, %1}, %2;" : "=f"(lo), "=f"(hi) : "l"(v));
    return lo + hi;
}
__device__ __forceinline__ ull fpack(float lo, float hi) {
    ull v;
    asm("mov.b64 %0, {%1, %2};" : "=l"(v) : "f"(lo), "f"(hi));
    return v;
}
__device__ __forceinline__ float tanhapx(float x) {
    float y;
    asm("tanh.approx.f32 %0, %1;" : "=f"(y) : "f"(x));
    return y;
}
__device__ __forceinline__ float fast_sig(float x) {
    return fmaf(tanhapx(0.5f * x), 0.5f, 0.5f);
}

// ---------------- kernel 1: gi0 = x @ W_ih0^T + b_ih0 ----------------
static constexpr int GI_ROWS = 512;

__global__ __launch_bounds__(128, 4)
void gi0_kernel(const float* __restrict__ x,
                const float* __restrict__ w_ih0,
                const float* __restrict__ b_ih0)
{
    __shared__ ull   s_xu[GI_ROWS * 11];   // 9 pairs + pad to 11 -> conflict-free
    __shared__ ull   s_w[36][9];
    __shared__ float s_b[36];

    const int tid = threadIdx.x;
    for (int i = tid; i < 36 * 9; i += 128) {
        const int j = i / 9, k = i % 9;
        s_w[j][k] = *(const ull*)(w_ih0 + j * IN_DIM + 2 * k);
    }
    if (tid < 36) s_b[tid] = b_ih0[tid];

    const size_t row0 = (size_t)blockIdx.x * GI_ROWS;
    const float* xg = x + row0 * IN_DIM;
    for (int i = tid; i < GI_ROWS * 9; i += 128) {
        const int r = i / 9, p = i % 9;
        s_xu[r * 11 + p] = *(const ull*)(xg + r * IN_DIM + 2 * p);
    }
    __syncthreads();

    ull xp[4][9];
#pragma unroll
    for (int j = 0; j < 4; ++j) {
        const ull* row = s_xu + (tid + j * 128) * 11;
#pragma unroll
        for (int k = 0; k < 9; ++k) xp[j][k] = row[k];
    }

#pragma unroll
    for (int u = 0; u < HID; ++u) {
        float res[4][3];
#pragma unroll
        for (int g = 0; g < 3; ++g) {
            const int jrow = g * HID + u;
            ull w[9];
#pragma unroll
            for (int k = 0; k < 9; ++k) w[k] = s_w[jrow][k];
            const float b = s_b[jrow];
#pragma unroll
            for (int j = 0; j < 4; ++j) {
                ull acc = fpack(b, 0.0f);
#pragma unroll
                for (int k = 0; k < 9; ++k) acc = ffma2(xp[j][k], w[k], acc);
                res[j][g] = f2sum(acc);
            }
        }
        float4* plane = g_gi0 + (size_t)u * NROWS + row0;
#pragma unroll
        for (int j = 0; j < 4; ++j)
            plane[tid + j * 128] = make_float4(res[j][0], res[j][1], res[j][2], 0.0f);
    }
}

// ---------------- kernel 2: recurrent scan ----------------
// 32-thread blocks: 2 groups of 16 lanes, 2 batches per group -> 4 batches.
// 1024 blocks spread evenly (~6.9/SM) over 148 SMs.
static constexpr int S_THREADS = 32;
static constexpr int S_GRID    = BATCH / 4;   // 1024 blocks

__global__ __launch_bounds__(S_THREADS, 8)
void gru_scan_kernel(const float* __restrict__ w_hh0, const float* __restrict__ b_hh0,
                     const float* __restrict__ w_ih1, const float* __restrict__ w_hh1,
                     const float* __restrict__ b_ih1, const float* __restrict__ b_hh1,
                     const float* __restrict__ fc_w, const float* __restrict__ fc_b,
                     float* __restrict__ out)
{
    __shared__ __align__(16) float s_h1[2][2][HID];   // [group][batch][unit]
    __shared__ __align__(16) float s_h2[2][2][HID];

    const int tid   = threadIdx.x;
    const int grp_l = tid >> 4;
    const int sub   = tid & 15;
    const int u     = (sub < HID) ? sub : HID - 1;
    const int bA    = blockIdx.x * 4 + grp_l * 2;
    const int bB    = bA + 1;

    // All recurrent weights in registers (f32x2 pairs).
    ull whh0[3][6], wih1[3][6], whh1[3][6];
#pragma unroll
    for (int g = 0; g < 3; ++g) {
        const ull* p0 = (const ull*)(w_hh0 + (g * HID + u) * HID);
        const ull* p1 = (const ull*)(w_ih1 + (g * HID + u) * HID);
        const ull* p2 = (const ull*)(w_hh1 + (g * HID + u) * HID);
#pragma unroll
        for (int i = 0; i < 6; ++i) {
            whh0[g][i] = p0[i]; wih1[g][i] = p1[i]; whh1[g][i] = p2[i];
        }
    }

    const float bh0r = b_hh0[u];
    const float bh0z = b_hh0[HID + u];
    const ull pbh0n = fpack(b_hh0[2 * HID + u], 0.0f);
    const ull pb2r  = fpack(b_ih1[u]           + b_hh1[u],          0.0f);
    const ull pb2z  = fpack(b_ih1[HID + u]     + b_hh1[HID + u],    0.0f);
    const ull pb2in = fpack(b_ih1[2 * HID + u], 0.0f);
    const ull pb2hn = fpack(b_hh1[2 * HID + u], 0.0f);
    const float fcb = fc_b[0];
    ull fcwp[6];
#pragma unroll
    for (int i = 0; i < 6; ++i) fcwp[i] = *(const ull*)(fc_w + 2 * i);

    ull h1A[6], h1B[6], h2A[6], h2B[6];
#pragma unroll
    for (int i = 0; i < 6; ++i) { h1A[i] = h1B[i] = h2A[i] = h2B[i] = 0ull; }
    float hp1A = 0.0f, hp1B = 0.0f, hp2A = 0.0f, hp2B = 0.0f;

    const float4* gpA = g_gi0 + (size_t)u * NROWS + (size_t)bA * SEQ;
    const float4* gpB = g_gi0 + (size_t)u * NROWS + (size_t)bB * SEQ;

    float4 gcA = gpA[0];
    float4 gcB = gpB[0];

#pragma unroll 1
    for (int t = 0; t < SEQ; ++t) {
        const int tn = (t + 1 < SEQ) ? (t + 1) : t;
        const float4 gnA = gpA[tn];
        const float4 gnB = gpB[tn];

        // ---- layer-2 hh dots from PREVIOUS h2 ----
        ull prA = pb2r, pzA = pb2z, pnA = pb2hn;
        ull prB = pb2r, pzB = pb2z, pnB = pb2hn;
#pragma unroll
        for (int i = 0; i < 6; ++i) {
            prA = ffma2(h2A[i], whh1[0][i], prA); prB = ffma2(h2B[i], whh1[0][i], prB);
            pzA = ffma2(h2A[i], whh1[1][i], pzA); pzB = ffma2(h2B[i], whh1[1][i], pzB);
            pnA = ffma2(h2A[i], whh1[2][i], pnA); pnB = ffma2(h2B[i], whh1[2][i], pnB);
        }
        const float a2hnA = f2sum(pnA);
        const float a2hnB = f2sum(pnB);

        // ---- layer 1 ----
        ull qrA = fpack(gcA.x, bh0r), qzA = fpack(gcA.y, bh0z), qnA = pbh0n;
        ull qrB = fpack(gcB.x, bh0r), qzB = fpack(gcB.y, bh0z), qnB = pbh0n;
#pragma unroll
        for (int i = 0; i < 6; ++i) {
            qrA = ffma2(h1A[i], whh0[0][i], qrA); qrB = ffma2(h1B[i], whh0[0][i], qrB);
            qzA = ffma2(h1A[i], whh0[1][i], qzA); qzB = ffma2(h1B[i], whh0[1][i], qzB);
            qnA = ffma2(h1A[i], whh0[2][i], qnA); qnB = ffma2(h1B[i], whh0[2][i], qnB);
        }
        const float r1A = fast_sig(f2sum(qrA));
        const float r1B = fast_sig(f2sum(qrB));
        const float z1A = fast_sig(f2sum(qzA));
        const float z1B = fast_sig(f2sum(qzB));
        const float n1A = tanhapx(fmaf(r1A, f2sum(qnA), gcA.z));
        const float n1B = tanhapx(fmaf(r1B, f2sum(qnB), gcB.z));
        const float hn1A = fmaf(z1A, hp1A - n1A, n1A);
        const float hn1B = fmaf(z1B, hp1B - n1B, n1B);
        hp1A = hn1A; hp1B = hn1B;

        if (sub < HID) { s_h1[grp_l][0][u] = hn1A; s_h1[grp_l][1][u] = hn1B; }
        __syncwarp();
        {
            const ulonglong2* pa = (const ulonglong2*)s_h1[grp_l][0];
            const ulonglong2* pb = (const ulonglong2*)s_h1[grp_l][1];
            const ulonglong2 a0 = pa[0], a1 = pa[1], a2 = pa[2];
            const ulonglong2 b0 = pb[0], b1 = pb[1], b2 = pb[2];
            h1A[0] = a0.x; h1A[1] = a0.y; h1A[2] = a1.x;
            h1A[3] = a1.y; h1A[4] = a2.x; h1A[5] = a2.y;
            h1B[0] = b0.x; h1B[1] = b0.y; h1B[2] = b1.x;
            h1B[3] = b1.y; h1B[4] = b2.x; h1B[5] = b2.y;
        }

        // ---- layer-2 ih dots on fresh h1 ----
        ull piA = pb2in, piB = pb2in;
#pragma unroll
        for (int i = 0; i < 6; ++i) {
            prA = ffma2(h1A[i], wih1[0][i], prA); prB = ffma2(h1B[i], wih1[0][i], prB);
            pzA = ffma2(h1A[i], wih1[1][i], pzA); pzB = ffma2(h1B[i], wih1[1][i], pzB);
            piA = ffma2(h1A[i], wih1[2][i], piA); piB = ffma2(h1B[i], wih1[2][i], piB);
        }
        const float r2A = fast_sig(f2sum(prA));
        const float r2B = fast_sig(f2sum(prB));
        const float z2A = fast_sig(f2sum(pzA));
        const float z2B = fast_sig(f2sum(pzB));
        const float n2A = tanhapx(fmaf(r2A, a2hnA, f2sum(piA)));
        const float n2B = tanhapx(fmaf(r2B, a2hnB, f2sum(piB)));
        const float hn2A = fmaf(z2A, hp2A - n2A, n2A);
        const float hn2B = fmaf(z2B, hp2B - n2B, n2B);
        hp2A = hn2A; hp2B = hn2B;

        if (sub < HID) { s_h2[grp_l][0][u] = hn2A; s_h2[grp_l][1][u] = hn2B; }
        __syncwarp();
        {
            const ulonglong2* pa = (const ulonglong2*)s_h2[grp_l][0];
            const ulonglong2* pb = (const ulonglong2*)s_h2[grp_l][1];
            const ulonglong2 a0 = pa[0], a1 = pa[1], a2 = pa[2];
            const ulonglong2 b0 = pb[0], b1 = pb[1], b2 = pb[2];
            h2A[0] = a0.x; h2A[1] = a0.y; h2A[2] = a1.x;
            h2A[3] = a1.y; h2A[4] = a2.x; h2A[5] = a2.y;
            h2B[0] = b0.x; h2B[1] = b0.y; h2B[2] = b1.x;
            h2B[3] = b1.y; h2B[4] = b2.x; h2B[5] = b2.y;
        }

        // ---- fc on idle lanes 12 (batch A) / 13 (batch B) ----
        if (sub == 12 || sub == 13) {
            const ull* hh = (sub == 12) ? h2A : h2B;
            ull acc = fpack(fcb, 0.0f);
#pragma unroll
            for (int i = 0; i < 6; ++i) acc = ffma2(hh[i], fcwp[i], acc);
            out[(size_t)((sub == 12) ? bA : bB) * SEQ + t] = f2sum(acc);
        }

        gcA = gnA; gcB = gnB;
    }
}

extern "C" void kernel_launch(void* const* d_in, const int* in_sizes, int n_in,
                              void* d_out, int out_size) {
    const float* x     = (const float*)d_in[0];
    const float* w_ih0 = (const float*)d_in[1];
    const float* w_hh0 = (const float*)d_in[2];
    const float* b_ih0 = (const float*)d_in[3];
    const float* b_hh0 = (const float*)d_in[4];
    const float* w_ih1 = (const float*)d_in[5];
    const float* w_hh1 = (const float*)d_in[6];
    const float* b_ih1 = (const float*)d_in[7];
    const float* b_hh1 = (const float*)d_in[8];
    const float* fc_w  = (const float*)d_in[9];
    const float* fc_b  = (const float*)d_in[10];
    float* out = (float*)d_out;

    gi0_kernel<<<(int)(NROWS / GI_ROWS), 128>>>(x, w_ih0, b_ih0);
    gru_scan_kernel<<<S_GRID, S_THREADS>>>(w_hh0, b_hh0, w_ih1, w_hh1,
                                           b_ih1, b_hh1, fc_w, fc_b, out);
}

// round 8
// speedup vs baseline: 2.2050x; 1.0081x over previous
#include <cuda_runtime.h>

// GRU_67714454389230: 2-layer GRU (H=12, IN=18) + fc(12->1), B=4096, T=512.
// Round 8: software-pipeline the two GRU layers. Each scan iteration computes
// layer2(t) and layer1(t+1) CONCURRENTLY (they only depend on h1[t], h2[t-1]),
// then does one combined smem exchange -> critical path per step is ONE GRU
// cell, not two, and FMA-chain ILP doubles. gi0 scratch packed to 12B/elem
// (ull(r,z) plane + float(n) plane).

static constexpr int IN_DIM = 18;
static constexpr int HID    = 12;
static constexpr int BATCH  = 4096;
static constexpr int SEQ    = 512;
static constexpr size_t NROWS = (size_t)BATCH * SEQ;   // 2,097,152

typedef unsigned long long ull;

// plane layouts, row = b*SEQ + t
__device__ ull   g_gi_rz[HID * NROWS];   // pack(gi_r, gi_z)
__device__ float g_gi_n [HID * NROWS];

// ---------------- helpers ----------------
__device__ __forceinline__ ull ffma2(ull a, ull b, ull c) {
    ull d;
    asm("fma.rn.f32x2 %0, %1, %2, %3;" : "=l"(d) : "l"(a), "l"(b), "l"(c));
    return d;
}
__device__ __forceinline__ float f2sum(ull v) {
    float lo, hi;
    asm("mov.b64 {%0, %1}, %2;" : "=f"(lo), "=f"(hi) : "l"(v));
    return lo + hi;
}
__device__ __forceinline__ ull fpack(float lo, float hi) {
    ull v;
    asm("mov.b64 %0, {%1, %2};" : "=l"(v) : "f"(lo), "f"(hi));
    return v;
}
__device__ __forceinline__ void funpack(ull v, float& lo, float& hi) {
    asm("mov.b64 {%0, %1}, %2;" : "=f"(lo), "=f"(hi) : "l"(v));
}
__device__ __forceinline__ float tanhapx(float x) {
    float y;
    asm("tanh.approx.f32 %0, %1;" : "=f"(y) : "f"(x));
    return y;
}
__device__ __forceinline__ float fast_sig(float x) {
    return fmaf(tanhapx(0.5f * x), 0.5f, 0.5f);
}

// ---------------- kernel 1: gi0 = x @ W_ih0^T + b_ih0 ----------------
static constexpr int GI_ROWS = 512;

__global__ __launch_bounds__(128, 4)
void gi0_kernel(const float* __restrict__ x,
                const float* __restrict__ w_ih0,
                const float* __restrict__ b_ih0)
{
    __shared__ ull   s_xu[GI_ROWS * 11];   // 9 pairs + pad to 11 -> conflict-free
    __shared__ ull   s_w[36][9];
    __shared__ float s_b[36];

    const int tid = threadIdx.x;
    for (int i = tid; i < 36 * 9; i += 128) {
        const int j = i / 9, k = i % 9;
        s_w[j][k] = *(const ull*)(w_ih0 + j * IN_DIM + 2 * k);
    }
    if (tid < 36) s_b[tid] = b_ih0[tid];

    const size_t row0 = (size_t)blockIdx.x * GI_ROWS;
    const float* xg = x + row0 * IN_DIM;
    for (int i = tid; i < GI_ROWS * 9; i += 128) {
        const int r = i / 9, p = i % 9;
        s_xu[r * 11 + p] = *(const ull*)(xg + r * IN_DIM + 2 * p);
    }
    __syncthreads();

    ull xp[4][9];
#pragma unroll
    for (int j = 0; j < 4; ++j) {
        const ull* row = s_xu + (tid + j * 128) * 11;
#pragma unroll
        for (int k = 0; k < 9; ++k) xp[j][k] = row[k];
    }

#pragma unroll
    for (int u = 0; u < HID; ++u) {
        float res[4][3];
#pragma unroll
        for (int g = 0; g < 3; ++g) {
            const int jrow = g * HID + u;
            ull w[9];
#pragma unroll
            for (int k = 0; k < 9; ++k) w[k] = s_w[jrow][k];
            const float b = s_b[jrow];
#pragma unroll
            for (int j = 0; j < 4; ++j) {
                ull acc = fpack(b, 0.0f);
#pragma unroll
                for (int k = 0; k < 9; ++k) acc = ffma2(xp[j][k], w[k], acc);
                res[j][g] = f2sum(acc);
            }
        }
        ull*   prz = g_gi_rz + (size_t)u * NROWS + row0;
        float* pn  = g_gi_n  + (size_t)u * NROWS + row0;
#pragma unroll
        for (int j = 0; j < 4; ++j) {
            prz[tid + j * 128] = fpack(res[j][0], res[j][1]);
            pn [tid + j * 128] = res[j][2];
        }
    }
}

// ---------------- kernel 2: recurrent scan (layer-pipelined) ----------------
// 32-thread blocks: 2 groups of 16 lanes, 2 batches per group -> 4 batches.
static constexpr int S_THREADS = 32;
static constexpr int S_GRID    = BATCH / 4;   // 1024 blocks

__global__ __launch_bounds__(S_THREADS, 8)
void gru_scan_kernel(const float* __restrict__ w_hh0, const float* __restrict__ b_hh0,
                     const float* __restrict__ w_ih1, const float* __restrict__ w_hh1,
                     const float* __restrict__ b_ih1, const float* __restrict__ b_hh1,
                     const float* __restrict__ fc_w, const float* __restrict__ fc_b,
                     float* __restrict__ out)
{
    __shared__ __align__(16) float s_h1[2][2][HID];   // [group][batch][unit]
    __shared__ __align__(16) float s_h2[2][2][HID];
    __shared__ float s_fcw[HID];

    const int tid   = threadIdx.x;
    const int grp_l = tid >> 4;
    const int sub   = tid & 15;
    const int u     = (sub < HID) ? sub : HID - 1;
    const int bA    = blockIdx.x * 4 + grp_l * 2;
    const int bB    = bA + 1;

    if (tid < HID) s_fcw[tid] = fc_w[tid];

    // All recurrent weights in registers (f32x2 pairs).
    ull whh0[3][6], wih1[3][6], whh1[3][6];
#pragma unroll
    for (int g = 0; g < 3; ++g) {
        const ull* p0 = (const ull*)(w_hh0 + (g * HID + u) * HID);
        const ull* p1 = (const ull*)(w_ih1 + (g * HID + u) * HID);
        const ull* p2 = (const ull*)(w_hh1 + (g * HID + u) * HID);
#pragma unroll
        for (int i = 0; i < 6; ++i) {
            whh0[g][i] = p0[i]; wih1[g][i] = p1[i]; whh1[g][i] = p2[i];
        }
    }

    const float bh0r = b_hh0[u];
    const float bh0z = b_hh0[HID + u];
    const float bh0n = b_hh0[2 * HID + u];
    const ull pbh0n = fpack(bh0n, 0.0f);
    const ull pb2r  = fpack(b_ih1[u]           + b_hh1[u],          0.0f);
    const ull pb2z  = fpack(b_ih1[HID + u]     + b_hh1[HID + u],    0.0f);
    const ull pb2in = fpack(b_ih1[2 * HID + u], 0.0f);
    const ull pb2hn = fpack(b_hh1[2 * HID + u], 0.0f);
    const float fcb = fc_b[0];

    const ull*   grzA = g_gi_rz + (size_t)u * NROWS + (size_t)bA * SEQ;
    const ull*   grzB = g_gi_rz + (size_t)u * NROWS + (size_t)bB * SEQ;
    const float* gnpA = g_gi_n  + (size_t)u * NROWS + (size_t)bA * SEQ;
    const float* gnpB = g_gi_n  + (size_t)u * NROWS + (size_t)bB * SEQ;

    ull H1A[6], H1B[6], H2A[6], H2B[6];
#pragma unroll
    for (int i = 0; i < 6; ++i) { H1A[i] = H1B[i] = H2A[i] = H2B[i] = 0ull; }
    float hp1A, hp1B, hp2A = 0.0f, hp2B = 0.0f;
    __syncthreads();   // s_fcw + weight loads visible

    // ---- prologue: h1[0] = GRU1(gi0[0], 0)  (hh contribution = bias only) ----
    {
        float grA, gzA, grB, gzB;
        funpack(grzA[0], grA, gzA);
        funpack(grzB[0], grB, gzB);
        const float gnA0 = gnpA[0], gnB0 = gnpB[0];
        const float rA = fast_sig(grA + bh0r);
        const float rB = fast_sig(grB + bh0r);
        const float zA = fast_sig(gzA + bh0z);
        const float zB = fast_sig(gzB + bh0z);
        const float nA = tanhapx(fmaf(rA, bh0n, gnA0));
        const float nB = tanhapx(fmaf(rB, bh0n, gnB0));
        hp1A = nA - zA * nA;
        hp1B = nB - zB * nB;
        if (sub < HID) { s_h1[grp_l][0][u] = hp1A; s_h1[grp_l][1][u] = hp1B; }
        __syncwarp();
        const ulonglong2* pa = (const ulonglong2*)s_h1[grp_l][0];
        const ulonglong2* pb = (const ulonglong2*)s_h1[grp_l][1];
        const ulonglong2 a0 = pa[0], a1 = pa[1], a2 = pa[2];
        const ulonglong2 b0 = pb[0], b1 = pb[1], b2 = pb[2];
        H1A[0] = a0.x; H1A[1] = a0.y; H1A[2] = a1.x;
        H1A[3] = a1.y; H1A[4] = a2.x; H1A[5] = a2.y;
        H1B[0] = b0.x; H1B[1] = b0.y; H1B[2] = b1.x;
        H1B[3] = b1.y; H1B[4] = b2.x; H1B[5] = b2.y;
    }

    // gi for t+1=1 (consumed by layer1 inside iteration t=0)
    ull   rzA = grzA[1], rzB = grzB[1];
    float gnA = gnpA[1], gnB = gnpB[1];

#pragma unroll 1
    for (int t = 0; t < SEQ; ++t) {
        const int tn = (t + 2 < SEQ) ? (t + 2) : SEQ - 1;
        const ull   rzA_n = grzA[tn];
        const ull   rzB_n = grzB[tn];
        const float gnA_n = gnpA[tn];
        const float gnB_n = gnpB[tn];

        // ======== layer 2 for step t (uses H1 = h1[t], H2 = h2[t-1]) ========
        ull prA = pb2r, pzA = pb2z, pnA = pb2hn, piA = pb2in;
        ull prB = pb2r, pzB = pb2z, pnB = pb2hn, piB = pb2in;
        // ======== layer 1 for step t+1 (uses gi(t+1), H1 = h1[t]) ========
        float grA, gzA2, grB, gzB2;
        funpack(rzA, grA, gzA2);
        funpack(rzB, grB, gzB2);
        ull qrA = fpack(grA, bh0r), qzA = fpack(gzA2, bh0z), qnA = pbh0n;
        ull qrB = fpack(grB, bh0r), qzB = fpack(gzB2, bh0z), qnB = pbh0n;

#pragma unroll
        for (int i = 0; i < 6; ++i) {
            // layer2 hh dots (H2)
            prA = ffma2(H2A[i], whh1[0][i], prA); prB = ffma2(H2B[i], whh1[0][i], prB);
            pzA = ffma2(H2A[i], whh1[1][i], pzA); pzB = ffma2(H2B[i], whh1[1][i], pzB);
            pnA = ffma2(H2A[i], whh1[2][i], pnA); pnB = ffma2(H2B[i], whh1[2][i], pnB);
            // layer2 ih dots (H1)
            prA = ffma2(H1A[i], wih1[0][i], prA); prB = ffma2(H1B[i], wih1[0][i], prB);
            pzA = ffma2(H1A[i], wih1[1][i], pzA); pzB = ffma2(H1B[i], wih1[1][i], pzB);
            piA = ffma2(H1A[i], wih1[2][i], piA); piB = ffma2(H1B[i], wih1[2][i], piB);
            // layer1 hh dots (H1)
            qrA = ffma2(H1A[i], whh0[0][i], qrA); qrB = ffma2(H1B[i], whh0[0][i], qrB);
            qzA = ffma2(H1A[i], whh0[1][i], qzA); qzB = ffma2(H1B[i], whh0[1][i], qzB);
            qnA = ffma2(H1A[i], whh0[2][i], qnA); qnB = ffma2(H1B[i], whh0[2][i], qnB);
        }

        // layer2 activations -> hn2 = h2[t][u]
        const float r2A = fast_sig(f2sum(prA));
        const float r2B = fast_sig(f2sum(prB));
        const float z2A = fast_sig(f2sum(pzA));
        const float z2B = fast_sig(f2sum(pzB));
        const float n2A = tanhapx(fmaf(r2A, f2sum(pnA), f2sum(piA)));
        const float n2B = tanhapx(fmaf(r2B, f2sum(pnB), f2sum(piB)));
        const float hn2A = fmaf(z2A, hp2A - n2A, n2A);
        const float hn2B = fmaf(z2B, hp2B - n2B, n2B);
        hp2A = hn2A; hp2B = hn2B;

        // layer1 activations -> hn1 = h1[t+1][u]
        const float r1A = fast_sig(f2sum(qrA));
        const float r1B = fast_sig(f2sum(qrB));
        const float z1A = fast_sig(f2sum(qzA));
        const float z1B = fast_sig(f2sum(qzB));
        const float n1A = tanhapx(fmaf(r1A, f2sum(qnA), gnA));
        const float n1B = tanhapx(fmaf(r1B, f2sum(qnB), gnB));
        const float hn1A = fmaf(z1A, hp1A - n1A, n1A);
        const float hn1B = fmaf(z1B, hp1B - n1B, n1B);
        hp1A = hn1A; hp1B = hn1B;

        // ======== combined exchange ========
        if (sub < HID) {
            s_h1[grp_l][0][u] = hn1A; s_h1[grp_l][1][u] = hn1B;
            s_h2[grp_l][0][u] = hn2A; s_h2[grp_l][1][u] = hn2B;
        }
        __syncwarp();
        {
            const ulonglong2* pa = (const ulonglong2*)s_h1[grp_l][0];
            const ulonglong2* pb = (const ulonglong2*)s_h1[grp_l][1];
            const ulonglong2 a0 = pa[0], a1 = pa[1], a2 = pa[2];
            const ulonglong2 b0 = pb[0], b1 = pb[1], b2 = pb[2];
            H1A[0] = a0.x; H1A[1] = a0.y; H1A[2] = a1.x;
            H1A[3] = a1.y; H1A[4] = a2.x; H1A[5] = a2.y;
            H1B[0] = b0.x; H1B[1] = b0.y; H1B[2] = b1.x;
            H1B[3] = b1.y; H1B[4] = b2.x; H1B[5] = b2.y;
        }
        {
            const ulonglong2* pa = (const ulonglong2*)s_h2[grp_l][0];
            const ulonglong2* pb = (const ulonglong2*)s_h2[grp_l][1];
            const ulonglong2 a0 = pa[0], a1 = pa[1], a2 = pa[2];
            const ulonglong2 b0 = pb[0], b1 = pb[1], b2 = pb[2];
            H2A[0] = a0.x; H2A[1] = a0.y; H2A[2] = a1.x;
            H2A[3] = a1.y; H2A[4] = a2.x; H2A[5] = a2.y;
            H2B[0] = b0.x; H2B[1] = b0.y; H2B[2] = b1.x;
            H2B[3] = b1.y; H2B[4] = b2.x; H2B[5] = b2.y;
        }

        // ======== fc(h2[t]) on idle lanes 12 (A) / 13 (B) ========
        if (sub >= 12 && sub < 14) {
            const ull* hh = (sub == 12) ? H2A : H2B;
            ull acc = fpack(fcb, 0.0f);
#pragma unroll
            for (int i = 0; i < 6; ++i)
                acc = ffma2(hh[i], *(const ull*)&s_fcw[2 * i], acc);
            out[(size_t)((sub == 12) ? bA : bB) * SEQ + t] = f2sum(acc);
        }

        rzA = rzA_n; rzB = rzB_n; gnA = gnA_n; gnB = gnB_n;
    }
}

extern "C" void kernel_launch(void* const* d_in, const int* in_sizes, int n_in,
                              void* d_out, int out_size) {
    const float* x     = (const float*)d_in[0];
    const float* w_ih0 = (const float*)d_in[1];
    const float* w_hh0 = (const float*)d_in[2];
    const float* b_ih0 = (const float*)d_in[3];
    const float* b_hh0 = (const float*)d_in[4];
    const float* w_ih1 = (const float*)d_in[5];
    const float* w_hh1 = (const float*)d_in[6];
    const float* b_ih1 = (const float*)d_in[7];
    const float* b_hh1 = (const float*)d_in[8];
    const float* fc_w  = (const float*)d_in[9];
    const float* fc_b  = (const float*)d_in[10];
    float* out = (float*)d_out;

    gi0_kernel<<<(int)(NROWS / GI_ROWS), 128>>>(x, w_ih0, b_ih0);
    gru_scan_kernel<<<S_GRID, S_THREADS>>>(w_hh0, b_hh0, w_ih1, w_hh1,
                                           b_ih1, b_hh1, fc_w, fc_b, out);
}